// round 4
// baseline (speedup 1.0000x reference)
#include <cuda_runtime.h>

typedef unsigned long long ull;

// ---------------- problem dimensions ----------------
static constexpr int D1=41, H1=200, W1=176; static constexpr int N1=D1*H1*W1;   // 1,443,200
static constexpr int D2=21, H2=100, W2=88;  static constexpr int N2=D2*H2*W2;   // 184,800
static constexpr int D3=11, H3=50,  W3=44;  static constexpr int N3=D3*H3*W3;   // 24,200
static constexpr int D4=5,  H4=25,  W4=22;  static constexpr int N4=D4*H4*W4;   // 2,750
static constexpr int D5=2,  H5=25,  W5=22;  static constexpr int N5=D5*H5*W5;   // 1,100

// ---------------- static device scratch ----------------
__device__ __align__(16) float g_bufA[16 * N1];   // 92.4 MB ping
__device__ __align__(16) float g_bufB[16 * N1];   // 92.4 MB pong
__device__ float g_mask2[N2];
__device__ float g_mask3[N3];
__device__ float g_mask4[N4];
__device__ float g_mask5[N5];
__device__ __align__(16) float g_wr[710592];      // reordered weights, all 12 layers
__device__ int   g_list[N1];
__device__ int   g_cnt;

// ---------------- f32x2 helpers (FFMA2 on sm_103a) ----------------
__device__ __forceinline__ ull f2_dup(float v) {
    ull r; asm("mov.b64 %0, {%1, %1};" : "=l"(r) : "f"(v)); return r;
}
__device__ __forceinline__ void f2_unpack(ull v, float& lo, float& hi) {
    asm("mov.b64 {%0, %1}, %2;" : "=f"(lo), "=f"(hi) : "l"(v));
}
#define FMA_F32X2(d, a, b, c) \
    asm("fma.rn.f32x2 %0, %1, %2, %3;" : "=l"(d) : "l"(a), "l"(b), "l"(c))

// ---------------- helpers ----------------
__global__ void reset_cnt_kernel() { g_cnt = 0; }

__global__ void compact_kernel(const float* __restrict__ mask) {
    int i = blockIdx.x * blockDim.x + threadIdx.x;
    if (i < N1 && mask[i] != 0.0f) {
        int p = atomicAdd(&g_cnt, 1);
        g_list[p] = i;
    }
}

// reorder w [CO][CI][KD][KH][KW] -> wr [CI*K3 + k][CO]  (co fastest, 64/128-bit friendly)
__global__ void prep_w_kernel(const float* __restrict__ w, float* __restrict__ wr,
                              int CI, int CO, int K3) {
    int t = blockIdx.x * blockDim.x + threadIdx.x;
    int n = CO * CI * K3;
    if (t < n) {
        int k  = t % K3;
        int r  = t / K3;
        int ci = r % CI;
        int co = r / CI;
        wr[(ci * K3 + k) * CO + co] = w[t];
    }
}

__global__ void mask_pool_kernel(const float* __restrict__ mi, float* __restrict__ mo,
                                 int ID, int IH, int IW, int OD, int OH, int OW,
                                 int KD, int KH, int KW, int SD, int SH, int SW,
                                 int PD, int PH, int PW) {
    int o = blockIdx.x * blockDim.x + threadIdx.x;
    int n = OD * OH * OW;
    if (o >= n) return;
    int x = o % OW; int t = o / OW; int y = t % OH; int z = t / OH;
    float mx = 0.0f;
    for (int kz = 0; kz < KD; kz++) {
        int zi = z * SD - PD + kz; if ((unsigned)zi >= (unsigned)ID) continue;
        for (int ky = 0; ky < KH; ky++) {
            int yi = y * SH - PH + ky; if ((unsigned)yi >= (unsigned)IH) continue;
            for (int kx = 0; kx < KW; kx++) {
                int xi = x * SW - PW + kx; if ((unsigned)xi >= (unsigned)IW) continue;
                mx = fmaxf(mx, mi[(zi * IH + yi) * IW + xi]);
            }
        }
    }
    mo[o] = (mx > 0.0f) ? 1.0f : 0.0f;
}

// ---------------- sparse gather subm conv (3x3x3, s1, p1), 8 co per thread ----------------
template<int CI, int CO>
__global__ void subm_gather_f2(const float* __restrict__ in, const float* __restrict__ wr,
                               const float* __restrict__ bn, float* __restrict__ out,
                               int D, int H, int W) {
    const int q = threadIdx.x;               // [0, CO/8)
    const int co0 = 8 * q;
    const int n = g_cnt;
    const ull* __restrict__ wq = reinterpret_cast<const ull*>(wr);

    for (int e = blockIdx.x * blockDim.y + threadIdx.y; e < n; e += gridDim.x * blockDim.y) {
        const int idx = g_list[e];
        const int x  = idx % W;
        const int zy = idx / W;
        const int y  = zy % H;
        const int z  = zy / H;

        ull acc[4] = {0ull, 0ull, 0ull, 0ull};
        for (int ci = 0; ci < CI; ci++) {
            #pragma unroll
            for (int kz = 0; kz < 3; kz++) {
                int zi = z - 1 + kz; if ((unsigned)zi >= (unsigned)D) continue;
                #pragma unroll
                for (int ky = 0; ky < 3; ky++) {
                    int yi = y - 1 + ky; if ((unsigned)yi >= (unsigned)H) continue;
                    const float* __restrict__ prow = in + ((ci * D + zi) * (long)H + yi) * W + x;
                    const int wbase = (((ci * 3 + kz) * 3 + ky) * 3 * CO + co0) >> 1;
                    #pragma unroll
                    for (int kx = 0; kx < 3; kx++) {
                        int xi = x - 1 + kx;
                        float iv = ((unsigned)xi < (unsigned)W) ? __ldg(prow + kx - 1) : 0.0f;
                        ull iv2 = f2_dup(iv);
                        const ull* wrow = wq + wbase + kx * (CO >> 1);
                        #pragma unroll
                        for (int j = 0; j < 4; j++) {
                            ull w2 = __ldg(wrow + j);
                            FMA_F32X2(acc[j], iv2, w2, acc[j]);
                        }
                    }
                }
            }
        }
        #pragma unroll
        for (int j = 0; j < 4; j++) {
            int ca = co0 + 2 * j, cb = ca + 1;
            float sca = bn[ca] * rsqrtf(bn[3 * CO + ca] + 1e-3f);
            float sha = bn[CO + ca] - bn[2 * CO + ca] * sca;
            float scb = bn[cb] * rsqrtf(bn[3 * CO + cb] + 1e-3f);
            float shb = bn[CO + cb] - bn[2 * CO + cb] * scb;
            float a0, a1; f2_unpack(acc[j], a0, a1);
            out[((ca * D + z) * (long)H + y) * W + x] = fmaxf(fmaf(a0, sca, sha), 0.0f);
            out[((cb * D + z) * (long)H + y) * W + x] = fmaxf(fmaf(a1, scb, shb), 0.0f);
        }
    }
}

// ---------------- dense tiled conv + BN + ReLU + mask, f32x2 over co ----------------
// block = (CO/CPT, ceil(OW/V)); thread computes V consecutive-x voxels x CPT channels.
template<int CI, int CO, int CPT, int V,
         int KD, int KH, int KW, int SD, int SH, int SW, int PD, int PH, int PW>
__global__ void conv_dense_f2(const float* __restrict__ in, const float* __restrict__ wr,
                              const float* __restrict__ bn, const float* __restrict__ omask,
                              float* __restrict__ out,
                              int ID, int IH, int IW, int OD, int OH, int OW) {
    constexpr int NSEG = (V - 1) * SW + KW;
    constexpr int NP = CPT / 2;
    const int q   = threadIdx.x;
    const int co0 = q * CPT;
    const int x0  = threadIdx.y * V;
    const int y   = blockIdx.y;
    const int z   = blockIdx.z;
    if (x0 >= OW) return;

    float m[V];
    const int obase = (z * OH + y) * OW;
    float msum = 0.0f;
    #pragma unroll
    for (int v = 0; v < V; v++) {
        m[v] = (x0 + v < OW) ? omask[obase + x0 + v] : 0.0f;
        msum += m[v];
    }
    const bool any = msum > 0.0f;

    ull acc[V][NP];
    #pragma unroll
    for (int v = 0; v < V; v++)
        #pragma unroll
        for (int j = 0; j < NP; j++) acc[v][j] = 0ull;

    if (any) {
        const int zi0 = z * SD - PD;
        const int yi0 = y * SH - PH;
        const int xi0 = x0 * SW - PW;
        const ull* __restrict__ wq = reinterpret_cast<const ull*>(wr);
        for (int ci = 0; ci < CI; ci++) {
            #pragma unroll
            for (int kz = 0; kz < KD; kz++) {
                int zi = zi0 + kz; if ((unsigned)zi >= (unsigned)ID) continue;
                #pragma unroll
                for (int ky = 0; ky < KH; ky++) {
                    int yi = yi0 + ky; if ((unsigned)yi >= (unsigned)IH) continue;
                    const float* __restrict__ prow = in + ((ci * ID + zi) * (long)IH + yi) * IW;
                    ull iv2[NSEG];
                    #pragma unroll
                    for (int s = 0; s < NSEG; s++) {
                        int xi = xi0 + s;
                        float f = ((unsigned)xi < (unsigned)IW) ? __ldg(prow + xi) : 0.0f;
                        iv2[s] = f2_dup(f);
                    }
                    const int wbase = (((ci * KD + kz) * KH + ky) * KW * CO + co0) >> 1;
                    #pragma unroll
                    for (int kx = 0; kx < KW; kx++) {
                        ull w2[NP];
                        #pragma unroll
                        for (int j = 0; j < NP; j++)
                            w2[j] = __ldg(wq + wbase + kx * (CO >> 1) + j);
                        #pragma unroll
                        for (int v = 0; v < V; v++) {
                            #pragma unroll
                            for (int j = 0; j < NP; j++)
                                FMA_F32X2(acc[v][j], iv2[v * SW + kx], w2[j], acc[v][j]);
                        }
                    }
                }
            }
        }
    }

    #pragma unroll
    for (int j = 0; j < NP; j++) {
        int ca = co0 + 2 * j, cb = ca + 1;
        float sca = bn[ca] * rsqrtf(bn[3 * CO + ca] + 1e-3f);
        float sha = bn[CO + ca] - bn[2 * CO + ca] * sca;
        float scb = bn[cb] * rsqrtf(bn[3 * CO + cb] + 1e-3f);
        float shb = bn[CO + cb] - bn[2 * CO + cb] * scb;
        float oa[V], ob[V];
        #pragma unroll
        for (int v = 0; v < V; v++) {
            float a0, a1; f2_unpack(acc[v][j], a0, a1);
            bool act = m[v] > 0.0f;
            oa[v] = act ? fmaxf(fmaf(a0, sca, sha), 0.0f) : 0.0f;
            ob[v] = act ? fmaxf(fmaf(a1, scb, shb), 0.0f) : 0.0f;
        }
        long ba = ((long)(ca * OD + z) * OH + y) * OW + x0;
        long bb = ((long)(cb * OD + z) * OH + y) * OW + x0;
        if constexpr (V == 4) {
            if (x0 + 4 <= OW && (x0 & 3) == 0 && (OW & 3) == 0) {
                *reinterpret_cast<float4*>(out + ba) = make_float4(oa[0], oa[1], oa[2], oa[3]);
                *reinterpret_cast<float4*>(out + bb) = make_float4(ob[0], ob[1], ob[2], ob[3]);
            } else {
                for (int v = 0; v < 4; v++) if (x0 + v < OW) {
                    out[ba + v] = oa[v]; out[bb + v] = ob[v];
                }
            }
        } else if constexpr (V == 2) {
            if (x0 + 2 <= OW && (x0 & 1) == 0 && (OW & 1) == 0) {
                *reinterpret_cast<float2*>(out + ba) = make_float2(oa[0], oa[1]);
                *reinterpret_cast<float2*>(out + bb) = make_float2(ob[0], ob[1]);
            } else {
                for (int v = 0; v < 2; v++) if (x0 + v < OW) {
                    out[ba + v] = oa[v]; out[bb + v] = ob[v];
                }
            }
        } else {
            for (int v = 0; v < V; v++) if (x0 + v < OW) {
                out[ba + v] = oa[v]; out[bb + v] = ob[v];
            }
        }
    }
}

// ---------------- launch ----------------
extern "C" void kernel_launch(void* const* d_in, const int* in_sizes, int n_in,
                              void* d_out, int out_size) {
    const float* x    = (const float*)d_in[0];
    const float* mask = (const float*)d_in[1];
    const float* W_[12];
    const float* B_[12];
    for (int i = 0; i < 12; i++) {
        W_[i] = (const float*)d_in[2 + 2 * i];
        B_[i] = (const float*)d_in[3 + 2 * i];
    }
    float* out = (float*)d_out;

    float *bufA, *bufB, *wr, *m2, *m3, *m4, *m5;
    cudaGetSymbolAddress((void**)&bufA, g_bufA);
    cudaGetSymbolAddress((void**)&bufB, g_bufB);
    cudaGetSymbolAddress((void**)&wr,   g_wr);
    cudaGetSymbolAddress((void**)&m2,   g_mask2);
    cudaGetSymbolAddress((void**)&m3,   g_mask3);
    cudaGetSymbolAddress((void**)&m4,   g_mask4);
    cudaGetSymbolAddress((void**)&m5,   g_mask5);

    static const int off[12] = {0, 1728, 8640, 22464, 50112, 77760, 133056,
                                243648, 354240, 464832, 575424, 686016};
    static const int wCI[12] = {4, 16, 16, 32, 32, 32, 64, 64, 64, 64, 64, 64};
    static const int wCO[12] = {16, 16, 32, 32, 32, 64, 64, 64, 64, 64, 64, 128};
    static const int wK3[12] = {27, 27, 27, 27, 27, 27, 27, 27, 27, 27, 27, 3};

    reset_cnt_kernel<<<1, 1>>>();
    for (int i = 0; i < 12; i++) {
        int n = wCO[i] * wCI[i] * wK3[i];
        prep_w_kernel<<<(n + 255) / 256, 256>>>(W_[i], wr + off[i], wCI[i], wCO[i], wK3[i]);
    }
    cudaMemsetAsync(bufA, 0, sizeof(float) * 16 * (size_t)N1, 0);
    cudaMemsetAsync(bufB, 0, sizeof(float) * 16 * (size_t)N1, 0);
    compact_kernel<<<(N1 + 255) / 256, 256>>>(mask);

    // L0: subm 4->16 (sparse gather), x -> bufA
    subm_gather_f2<4, 16><<<256, dim3(2, 128)>>>(x, wr + off[0], B_[0], bufA, D1, H1, W1);
    // L1: subm 16->16, bufA -> bufB
    subm_gather_f2<16, 16><<<256, dim3(2, 128)>>>(bufA, wr + off[1], B_[1], bufB, D1, H1, W1);

    // mask2 + L2: spconv 16->32 s2 p1, bufB -> bufA
    mask_pool_kernel<<<(N2 + 255) / 256, 256>>>(mask, m2, D1, H1, W1, D2, H2, W2,
                                                3, 3, 3, 2, 2, 2, 1, 1, 1);
    conv_dense_f2<16, 32, 8, 4, 3, 3, 3, 2, 2, 2, 1, 1, 1>
        <<<dim3(1, H2, D2), dim3(4, 22)>>>(bufB, wr + off[2], B_[2], m2, bufA,
                                           D1, H1, W1, D2, H2, W2);
    // L3, L4: subm 32->32
    conv_dense_f2<32, 32, 8, 4, 3, 3, 3, 1, 1, 1, 1, 1, 1>
        <<<dim3(1, H2, D2), dim3(4, 22)>>>(bufA, wr + off[3], B_[3], m2, bufB,
                                           D2, H2, W2, D2, H2, W2);
    conv_dense_f2<32, 32, 8, 4, 3, 3, 3, 1, 1, 1, 1, 1, 1>
        <<<dim3(1, H2, D2), dim3(4, 22)>>>(bufB, wr + off[4], B_[4], m2, bufA,
                                           D2, H2, W2, D2, H2, W2);

    // mask3 + L5: spconv 32->64 s2 p1, bufA -> bufB
    mask_pool_kernel<<<(N3 + 255) / 256, 256>>>(m2, m3, D2, H2, W2, D3, H3, W3,
                                                3, 3, 3, 2, 2, 2, 1, 1, 1);
    conv_dense_f2<32, 64, 8, 4, 3, 3, 3, 2, 2, 2, 1, 1, 1>
        <<<dim3(1, H3, D3), dim3(8, 11)>>>(bufA, wr + off[5], B_[5], m3, bufB,
                                           D2, H2, W2, D3, H3, W3);
    // L6, L7: subm 64->64
    conv_dense_f2<64, 64, 8, 4, 3, 3, 3, 1, 1, 1, 1, 1, 1>
        <<<dim3(1, H3, D3), dim3(8, 11)>>>(bufB, wr + off[6], B_[6], m3, bufA,
                                           D3, H3, W3, D3, H3, W3);
    conv_dense_f2<64, 64, 8, 4, 3, 3, 3, 1, 1, 1, 1, 1, 1>
        <<<dim3(1, H3, D3), dim3(8, 11)>>>(bufA, wr + off[7], B_[7], m3, bufB,
                                           D3, H3, W3, D3, H3, W3);

    // mask4 + L8: spconv 64->64 s2 pad(0,1,1), bufB -> bufA
    mask_pool_kernel<<<(N4 + 255) / 256, 256>>>(m3, m4, D3, H3, W3, D4, H4, W4,
                                                3, 3, 3, 2, 2, 2, 0, 1, 1);
    conv_dense_f2<64, 64, 4, 2, 3, 3, 3, 2, 2, 2, 0, 1, 1>
        <<<dim3(1, H4, D4), dim3(16, 11)>>>(bufB, wr + off[8], B_[8], m4, bufA,
                                            D3, H3, W3, D4, H4, W4);
    // L9, L10: subm 64->64
    conv_dense_f2<64, 64, 4, 2, 3, 3, 3, 1, 1, 1, 1, 1, 1>
        <<<dim3(1, H4, D4), dim3(16, 11)>>>(bufA, wr + off[9], B_[9], m4, bufB,
                                            D4, H4, W4, D4, H4, W4);
    conv_dense_f2<64, 64, 4, 2, 3, 3, 3, 1, 1, 1, 1, 1, 1>
        <<<dim3(1, H4, D4), dim3(16, 11)>>>(bufB, wr + off[10], B_[10], m4, bufA,
                                            D4, H4, W4, D4, H4, W4);

    // mask5 + L11: spconv 64->128 k(3,1,1) s(2,1,1) p0, bufA -> d_out
    mask_pool_kernel<<<(N5 + 255) / 256, 256>>>(m4, m5, D4, H4, W4, D5, H5, W5,
                                                3, 1, 1, 2, 1, 1, 0, 0, 0);
    conv_dense_f2<64, 128, 8, 2, 3, 1, 1, 2, 1, 1, 0, 0, 0>
        <<<dim3(1, H5, D5), dim3(16, 11)>>>(bufA, wr + off[11], B_[11], m5, out,
                                            D4, H4, W4, D5, H5, W5);
}

// round 5
// speedup vs baseline: 1.1352x; 1.1352x over previous
#include <cuda_runtime.h>

// ---------------- problem dimensions ----------------
static constexpr int D1=41, H1=200, W1=176; static constexpr int N1=D1*H1*W1;   // 1,443,200
static constexpr int D2=21, H2=100, W2=88;  static constexpr int N2=D2*H2*W2;   // 184,800
static constexpr int D3=11, H3=50,  W3=44;  static constexpr int N3=D3*H3*W3;   // 24,200
static constexpr int D4=5,  H4=25,  W4=22;  static constexpr int N4=D4*H4*W4;   // 2,750
static constexpr int D5=2,  H5=25,  W5=22;  static constexpr int N5=D5*H5*W5;   // 1,100

// ---------------- static device scratch ----------------
__device__ __align__(16) float g_bufA[16 * N1];   // 92.4 MB ping
__device__ __align__(16) float g_bufB[16 * N1];   // 92.4 MB pong
__device__ float g_mask2[N2];
__device__ float g_mask3[N3];
__device__ float g_mask4[N4];
__device__ float g_mask5[N5];
__device__ __align__(16) float g_wr[710592];      // reordered weights, all 12 layers
__device__ int   g_list[N1];
__device__ int   g_cnt;

// weight region metadata (floats)
__device__ __constant__ int c_off[12] = {0, 1728, 8640, 22464, 50112, 77760, 133056,
                                         243648, 354240, 464832, 575424, 686016};
__device__ __constant__ int c_CI[12] = {4, 16, 16, 32, 32, 32, 64, 64, 64, 64, 64, 64};
__device__ __constant__ int c_CO[12] = {16, 16, 32, 32, 32, 64, 64, 64, 64, 64, 64, 128};
__device__ __constant__ int c_K3[12] = {27, 27, 27, 27, 27, 27, 27, 27, 27, 27, 27, 3};

struct WPtrs { const float* w[12]; };

// ---------------- prelude kernels ----------------
__global__ void compact_kernel(const float* __restrict__ mask) {
    int i = blockIdx.x * blockDim.x + threadIdx.x;
    if (i < N1 && mask[i] != 0.0f) {
        int p = atomicAdd(&g_cnt, 1);
        g_list[p] = i;
    }
}

// all 12 layers in one kernel: w [CO][CI][K3] -> wr [CI*K3 + k][CO]
__global__ void prep_w_all(WPtrs p, float* __restrict__ wr) {
    int t = blockIdx.x * blockDim.x + threadIdx.x;
    if (t >= 710592) return;
    int L = 0;
    int base = 0;
    #pragma unroll
    for (int i = 0; i < 12; i++) {
        int n = c_CO[i] * c_CI[i] * c_K3[i];
        if (t >= base && t < base + n) { L = i; }
        if (t >= base + n) { }
        base += n;
    }
    // recompute base for layer L
    base = c_off[L];
    int local = t - base;
    int K3 = c_K3[L], CI = c_CI[L], CO = c_CO[L];
    int k  = local % K3;
    int r  = local / K3;
    int ci = r % CI;
    int co = r / CI;
    wr[base + (ci * K3 + k) * CO + co] = p.w[L][local];
}

__global__ void mask_pool_kernel(const float* __restrict__ mi, float* __restrict__ mo,
                                 int ID, int IH, int IW, int OD, int OH, int OW,
                                 int KD, int KH, int KW, int SD, int SH, int SW,
                                 int PD, int PH, int PW) {
    int o = blockIdx.x * blockDim.x + threadIdx.x;
    int n = OD * OH * OW;
    if (o >= n) return;
    int x = o % OW; int t = o / OW; int y = t % OH; int z = t / OH;
    float mx = 0.0f;
    for (int kz = 0; kz < KD; kz++) {
        int zi = z * SD - PD + kz; if ((unsigned)zi >= (unsigned)ID) continue;
        for (int ky = 0; ky < KH; ky++) {
            int yi = y * SH - PH + ky; if ((unsigned)yi >= (unsigned)IH) continue;
            for (int kx = 0; kx < KW; kx++) {
                int xi = x * SW - PW + kx; if ((unsigned)xi >= (unsigned)IW) continue;
                mx = fmaxf(mx, mi[(zi * IH + yi) * IW + xi]);
            }
        }
    }
    mo[o] = (mx > 0.0f) ? 1.0f : 0.0f;
}

// ---------------- sparse gather subm conv (3x3x3, stride1, pad1) ----------------
template<int CI, int CO>
__global__ void subm_gather_kernel(const float* __restrict__ in, const float* __restrict__ wr,
                                   const float* __restrict__ bn, float* __restrict__ out,
                                   int D, int H, int W) {
    const int q = threadIdx.x;       // [0, CO/4)
    const int n = g_cnt;
    for (int e = blockIdx.x * blockDim.y + threadIdx.y; e < n; e += gridDim.x * blockDim.y) {
        const int idx = g_list[e];
        const int x  = idx % W;
        const int zy = idx / W;
        const int y  = zy % H;
        const int z  = zy / H;

        float acc[4] = {0.f, 0.f, 0.f, 0.f};
        for (int ci = 0; ci < CI; ci++) {
            #pragma unroll
            for (int kz = 0; kz < 3; kz++) {
                int zi = z - 1 + kz; if ((unsigned)zi >= (unsigned)D) continue;
                #pragma unroll
                for (int ky = 0; ky < 3; ky++) {
                    int yi = y - 1 + ky; if ((unsigned)yi >= (unsigned)H) continue;
                    const float* __restrict__ prow = in + ((ci * D + zi) * (long)H + yi) * W + x;
                    const float* __restrict__ wrow = wr + ((ci * 3 + kz) * 3 + ky) * 3 * CO + 4 * q;
                    #pragma unroll
                    for (int kx = 0; kx < 3; kx++) {
                        int xi = x - 1 + kx;
                        float iv = ((unsigned)xi < (unsigned)W) ? __ldg(prow + kx - 1) : 0.0f;
                        float4 w4 = *reinterpret_cast<const float4*>(wrow + kx * CO);
                        acc[0] += iv * w4.x;
                        acc[1] += iv * w4.y;
                        acc[2] += iv * w4.z;
                        acc[3] += iv * w4.w;
                    }
                }
            }
        }
        #pragma unroll
        for (int j = 0; j < 4; j++) {
            int co = 4 * q + j;
            float g  = bn[co];
            float b  = bn[CO + co];
            float mu = bn[2 * CO + co];
            float vr = bn[3 * CO + co];
            float sc = g * rsqrtf(vr + 1e-3f);
            float sh = b - mu * sc;
            float val = fmaxf(acc[j] * sc + sh, 0.0f);
            out[((co * D + z) * (long)H + y) * W + x] = val;
        }
    }
}

// ---------------- dense tiled conv + BN + ReLU + mask ----------------
// block = (CO/4, OW/V, YB): thread computes V consecutive-x voxels x 4 channels;
// block covers one full x-row and YB y-rows. 352 threads = 11 full warps.
template<int CI, int CO, int V, int YB,
         int KD, int KH, int KW, int SD, int SH, int SW, int PD, int PH, int PW>
__global__ void __launch_bounds__(352, 2)
conv_dense_kernel(const float* __restrict__ in, const float* __restrict__ wr,
                  const float* __restrict__ bn, const float* __restrict__ omask,
                  float* __restrict__ out,
                  int ID, int IH, int IW, int OD, int OH, int OW) {
    constexpr int NSEG = (V - 1) * SW + KW;
    const int q  = threadIdx.x;                    // channel quad
    const int x0 = threadIdx.y * V;
    const int y  = blockIdx.y * YB + threadIdx.z;
    const int z  = blockIdx.z;
    if (y >= OH || x0 >= OW) return;

    float m[V];
    const int obase = (z * OH + y) * OW;
    float msum = 0.0f;
    #pragma unroll
    for (int v = 0; v < V; v++) {
        m[v] = (x0 + v < OW) ? omask[obase + x0 + v] : 0.0f;
        msum += m[v];
    }
    const bool any = msum > 0.0f;

    float acc[V][4];
    #pragma unroll
    for (int v = 0; v < V; v++)
        #pragma unroll
        for (int j = 0; j < 4; j++) acc[v][j] = 0.0f;

    if (any) {
        const int zi0 = z * SD - PD;
        const int yi0 = y * SH - PH;
        const int xi0 = x0 * SW - PW;
        for (int ci = 0; ci < CI; ci++) {
            #pragma unroll
            for (int kz = 0; kz < KD; kz++) {
                int zi = zi0 + kz; if ((unsigned)zi >= (unsigned)ID) continue;
                #pragma unroll
                for (int ky = 0; ky < KH; ky++) {
                    int yi = yi0 + ky; if ((unsigned)yi >= (unsigned)IH) continue;
                    const float* __restrict__ prow = in + ((ci * ID + zi) * (long)IH + yi) * IW;
                    float seg[NSEG];
                    #pragma unroll
                    for (int s = 0; s < NSEG; s++) {
                        int xi = xi0 + s;
                        seg[s] = ((unsigned)xi < (unsigned)IW) ? __ldg(prow + xi) : 0.0f;
                    }
                    const float* __restrict__ wrow =
                        wr + ((ci * KD + kz) * KH + ky) * KW * CO + 4 * q;
                    #pragma unroll
                    for (int kx = 0; kx < KW; kx++) {
                        float4 w4 = *reinterpret_cast<const float4*>(wrow + kx * CO);
                        #pragma unroll
                        for (int v = 0; v < V; v++) {
                            float iv = seg[v * SW + kx];
                            acc[v][0] += iv * w4.x;
                            acc[v][1] += iv * w4.y;
                            acc[v][2] += iv * w4.z;
                            acc[v][3] += iv * w4.w;
                        }
                    }
                }
            }
        }
    }

    #pragma unroll
    for (int j = 0; j < 4; j++) {
        int co = 4 * q + j;
        float g  = bn[co];
        float b  = bn[CO + co];
        float mu = bn[2 * CO + co];
        float vr = bn[3 * CO + co];
        float sc = g * rsqrtf(vr + 1e-3f);
        float sh = b - mu * sc;
        #pragma unroll
        for (int v = 0; v < V; v++) {
            int x = x0 + v;
            if (x < OW) {
                float val = (m[v] > 0.0f) ? fmaxf(acc[v][j] * sc + sh, 0.0f) : 0.0f;
                out[((co * OD + z) * (long)OH + y) * OW + x] = val;
            }
        }
    }
}

// ---------------- launch ----------------
extern "C" void kernel_launch(void* const* d_in, const int* in_sizes, int n_in,
                              void* d_out, int out_size) {
    const float* x    = (const float*)d_in[0];
    const float* mask = (const float*)d_in[1];
    WPtrs wp;
    const float* B_[12];
    for (int i = 0; i < 12; i++) {
        wp.w[i] = (const float*)d_in[2 + 2 * i];
        B_[i]   = (const float*)d_in[3 + 2 * i];
    }
    float* out = (float*)d_out;

    float *bufA, *bufB, *wr, *m2, *m3, *m4, *m5;
    int* cntp;
    cudaGetSymbolAddress((void**)&bufA, g_bufA);
    cudaGetSymbolAddress((void**)&bufB, g_bufB);
    cudaGetSymbolAddress((void**)&wr,   g_wr);
    cudaGetSymbolAddress((void**)&m2,   g_mask2);
    cudaGetSymbolAddress((void**)&m3,   g_mask3);
    cudaGetSymbolAddress((void**)&m4,   g_mask4);
    cudaGetSymbolAddress((void**)&m5,   g_mask5);
    cudaGetSymbolAddress((void**)&cntp, g_cnt);

    static const int off[12] = {0, 1728, 8640, 22464, 50112, 77760, 133056,
                                243648, 354240, 464832, 575424, 686016};

    // non-kernel prelude (memsets don't consume ncu launch slots)
    cudaMemsetAsync(cntp, 0, sizeof(int), 0);
    cudaMemsetAsync(bufA, 0, sizeof(float) * 16 * (size_t)N1, 0);
    cudaMemsetAsync(bufB, 0, sizeof(float) * 16 * (size_t)N1, 0);

    // launch 0: fused weight reorder; launch 1: compact
    prep_w_all<<<(710592 + 255) / 256, 256>>>(wp, wr);
    compact_kernel<<<(N1 + 255) / 256, 256>>>(mask);

    // launch 2,3: L0, L1 gather subm at full res
    subm_gather_kernel<4, 16><<<1024, dim3(4, 32)>>>(x, wr + off[0], B_[0], bufA, D1, H1, W1);
    subm_gather_kernel<16, 16><<<1024, dim3(4, 32)>>>(bufA, wr + off[1], B_[1], bufB, D1, H1, W1);

    // launch 4: mask2 ; launch 5: L2 (ncu -s 5 captures this)
    mask_pool_kernel<<<(N2 + 255) / 256, 256>>>(mask, m2, D1, H1, W1, D2, H2, W2,
                                                3, 3, 3, 2, 2, 2, 1, 1, 1);
    conv_dense_kernel<16, 32, 4, 2, 3, 3, 3, 2, 2, 2, 1, 1, 1>
        <<<dim3(1, (H2 + 1) / 2, D2), dim3(8, 22, 2)>>>(bufB, wr + off[2], B_[2], m2, bufA,
                                                        D1, H1, W1, D2, H2, W2);
    // L3, L4: subm 32->32 @ 21x100x88
    conv_dense_kernel<32, 32, 4, 2, 3, 3, 3, 1, 1, 1, 1, 1, 1>
        <<<dim3(1, (H2 + 1) / 2, D2), dim3(8, 22, 2)>>>(bufA, wr + off[3], B_[3], m2, bufB,
                                                        D2, H2, W2, D2, H2, W2);
    conv_dense_kernel<32, 32, 4, 2, 3, 3, 3, 1, 1, 1, 1, 1, 1>
        <<<dim3(1, (H2 + 1) / 2, D2), dim3(8, 22, 2)>>>(bufB, wr + off[4], B_[4], m2, bufA,
                                                        D2, H2, W2, D2, H2, W2);

    // mask3 + L5: spconv 32->64 s2 p1
    mask_pool_kernel<<<(N3 + 255) / 256, 256>>>(m2, m3, D2, H2, W2, D3, H3, W3,
                                                3, 3, 3, 2, 2, 2, 1, 1, 1);
    conv_dense_kernel<32, 64, 4, 2, 3, 3, 3, 2, 2, 2, 1, 1, 1>
        <<<dim3(1, (H3 + 1) / 2, D3), dim3(16, 11, 2)>>>(bufA, wr + off[5], B_[5], m3, bufB,
                                                         D2, H2, W2, D3, H3, W3);
    // L6, L7: subm 64->64 @ 11x50x44
    conv_dense_kernel<64, 64, 4, 2, 3, 3, 3, 1, 1, 1, 1, 1, 1>
        <<<dim3(1, (H3 + 1) / 2, D3), dim3(16, 11, 2)>>>(bufB, wr + off[6], B_[6], m3, bufA,
                                                         D3, H3, W3, D3, H3, W3);
    conv_dense_kernel<64, 64, 4, 2, 3, 3, 3, 1, 1, 1, 1, 1, 1>
        <<<dim3(1, (H3 + 1) / 2, D3), dim3(16, 11, 2)>>>(bufA, wr + off[7], B_[7], m3, bufB,
                                                         D3, H3, W3, D3, H3, W3);

    // mask4 + L8: spconv 64->64 s2 pad(0,1,1) -> 5x25x22
    mask_pool_kernel<<<(N4 + 255) / 256, 256>>>(m3, m4, D3, H3, W3, D4, H4, W4,
                                                3, 3, 3, 2, 2, 2, 0, 1, 1);
    conv_dense_kernel<64, 64, 2, 2, 3, 3, 3, 2, 2, 2, 0, 1, 1>
        <<<dim3(1, (H4 + 1) / 2, D4), dim3(16, 11, 2)>>>(bufB, wr + off[8], B_[8], m4, bufA,
                                                         D3, H3, W3, D4, H4, W4);
    // L9, L10: subm 64->64 @ 5x25x22
    conv_dense_kernel<64, 64, 2, 2, 3, 3, 3, 1, 1, 1, 1, 1, 1>
        <<<dim3(1, (H4 + 1) / 2, D4), dim3(16, 11, 2)>>>(bufA, wr + off[9], B_[9], m4, bufB,
                                                         D4, H4, W4, D4, H4, W4);
    conv_dense_kernel<64, 64, 2, 2, 3, 3, 3, 1, 1, 1, 1, 1, 1>
        <<<dim3(1, (H4 + 1) / 2, D4), dim3(16, 11, 2)>>>(bufB, wr + off[10], B_[10], m4, bufA,
                                                         D4, H4, W4, D4, H4, W4);

    // mask5 + L11: spconv 64->128 k(3,1,1) s(2,1,1) p0 -> d_out
    mask_pool_kernel<<<(N5 + 255) / 256, 256>>>(m4, m5, D4, H4, W4, D5, H5, W5,
                                                3, 1, 1, 2, 1, 1, 0, 0, 0);
    conv_dense_kernel<64, 128, 2, 1, 3, 1, 1, 2, 1, 1, 0, 0, 0>
        <<<dim3(1, H5, D5), dim3(32, 11, 1)>>>(bufA, wr + off[11], B_[11], m5, out,
                                               D4, H4, W4, D5, H5, W5);
}

// round 6
// speedup vs baseline: 1.2241x; 1.0783x over previous
#include <cuda_runtime.h>

typedef unsigned long long ull;

// ---------------- problem dimensions ----------------
static constexpr int D1=41, H1=200, W1=176; static constexpr int N1=D1*H1*W1;   // 1,443,200
static constexpr int D2=21, H2=100, W2=88;  static constexpr int N2=D2*H2*W2;   // 184,800
static constexpr int D3=11, H3=50,  W3=44;  static constexpr int N3=D3*H3*W3;   // 24,200
static constexpr int D4=5,  H4=25,  W4=22;  static constexpr int N4=D4*H4*W4;   // 2,750
static constexpr int D5=2,  H5=25,  W5=22;  static constexpr int N5=D5*H5*W5;   // 1,100

// ---------------- static device scratch ----------------
__device__ __align__(16) float g_bufA[16 * N1];   // 92.4 MB ping
__device__ __align__(16) float g_bufB[16 * N1];   // 92.4 MB pong
__device__ float g_mask2[N2];
__device__ float g_mask3[N3];
__device__ float g_mask4[N4];
__device__ float g_mask5[N5];
__device__ __align__(16) float g_wr[710592];      // reordered weights, all 12 layers
__device__ int   g_list[N1];
__device__ int   g_cnt;

// weight region metadata (floats)
__device__ __constant__ int c_off[12] = {0, 1728, 8640, 22464, 50112, 77760, 133056,
                                         243648, 354240, 464832, 575424, 686016};
__device__ __constant__ int c_CI[12] = {4, 16, 16, 32, 32, 32, 64, 64, 64, 64, 64, 64};
__device__ __constant__ int c_CO[12] = {16, 16, 32, 32, 32, 64, 64, 64, 64, 64, 64, 128};
__device__ __constant__ int c_K3[12] = {27, 27, 27, 27, 27, 27, 27, 27, 27, 27, 27, 3};

struct WPtrs { const float* w[12]; };

// ---------------- f32x2 helpers ----------------
__device__ __forceinline__ ull f2_dup(float v) {
    ull r; asm("mov.b64 %0, {%1, %1};" : "=l"(r) : "f"(v)); return r;
}
__device__ __forceinline__ void f2_unpack(ull v, float& lo, float& hi) {
    asm("mov.b64 {%0, %1}, %2;" : "=f"(lo), "=f"(hi) : "l"(v));
}
#define FMA_F32X2(d, a, b, c) \
    asm("fma.rn.f32x2 %0, %1, %2, %3;" : "=l"(d) : "l"(a), "l"(b), "l"(c))

// ---------------- prelude kernels ----------------
__global__ void compact_kernel(const float* __restrict__ mask) {
    int i = blockIdx.x * blockDim.x + threadIdx.x;
    if (i < N1 && mask[i] != 0.0f) {
        int p = atomicAdd(&g_cnt, 1);
        g_list[p] = i;
    }
}

// all 12 layers in one kernel: w [CO][CI][K3] -> wr [CI*K3 + k][CO]
__global__ void prep_w_all(WPtrs p, float* __restrict__ wr) {
    int t = blockIdx.x * blockDim.x + threadIdx.x;
    if (t >= 710592) return;
    int L = 0;
    int base = 0;
    #pragma unroll
    for (int i = 0; i < 12; i++) {
        int n = c_CO[i] * c_CI[i] * c_K3[i];
        if (t >= base && t < base + n) { L = i; }
        base += n;
    }
    base = c_off[L];
    int local = t - base;
    int K3 = c_K3[L], CI = c_CI[L], CO = c_CO[L];
    int k  = local % K3;
    int r  = local / K3;
    int ci = r % CI;
    int co = r / CI;
    wr[base + (ci * K3 + k) * CO + co] = p.w[L][local];
}

__global__ void mask_pool_kernel(const float* __restrict__ mi, float* __restrict__ mo,
                                 int ID, int IH, int IW, int OD, int OH, int OW,
                                 int KD, int KH, int KW, int SD, int SH, int SW,
                                 int PD, int PH, int PW) {
    int o = blockIdx.x * blockDim.x + threadIdx.x;
    int n = OD * OH * OW;
    if (o >= n) return;
    int x = o % OW; int t = o / OW; int y = t % OH; int z = t / OH;
    float mx = 0.0f;
    for (int kz = 0; kz < KD; kz++) {
        int zi = z * SD - PD + kz; if ((unsigned)zi >= (unsigned)ID) continue;
        for (int ky = 0; ky < KH; ky++) {
            int yi = y * SH - PH + ky; if ((unsigned)yi >= (unsigned)IH) continue;
            for (int kx = 0; kx < KW; kx++) {
                int xi = x * SW - PW + kx; if ((unsigned)xi >= (unsigned)IW) continue;
                mx = fmaxf(mx, mi[(zi * IH + yi) * IW + xi]);
            }
        }
    }
    mo[o] = (mx > 0.0f) ? 1.0f : 0.0f;
}

// ---------------- sparse gather subm conv (3x3x3, stride1, pad1) ----------------
template<int CI, int CO>
__global__ void subm_gather_kernel(const float* __restrict__ in, const float* __restrict__ wr,
                                   const float* __restrict__ bn, float* __restrict__ out,
                                   int D, int H, int W) {
    const int q = threadIdx.x;       // [0, CO/4)
    const int n = g_cnt;
    for (int e = blockIdx.x * blockDim.y + threadIdx.y; e < n; e += gridDim.x * blockDim.y) {
        const int idx = g_list[e];
        const int x  = idx % W;
        const int zy = idx / W;
        const int y  = zy % H;
        const int z  = zy / H;

        float acc[4] = {0.f, 0.f, 0.f, 0.f};
        for (int ci = 0; ci < CI; ci++) {
            #pragma unroll
            for (int kz = 0; kz < 3; kz++) {
                int zi = z - 1 + kz; if ((unsigned)zi >= (unsigned)D) continue;
                #pragma unroll
                for (int ky = 0; ky < 3; ky++) {
                    int yi = y - 1 + ky; if ((unsigned)yi >= (unsigned)H) continue;
                    const float* __restrict__ prow = in + ((ci * D + zi) * (long)H + yi) * W + x;
                    const float* __restrict__ wrow = wr + ((ci * 3 + kz) * 3 + ky) * 3 * CO + 4 * q;
                    #pragma unroll
                    for (int kx = 0; kx < 3; kx++) {
                        int xi = x - 1 + kx;
                        float iv = ((unsigned)xi < (unsigned)W) ? __ldg(prow + kx - 1) : 0.0f;
                        float4 w4 = *reinterpret_cast<const float4*>(wrow + kx * CO);
                        acc[0] += iv * w4.x;
                        acc[1] += iv * w4.y;
                        acc[2] += iv * w4.z;
                        acc[3] += iv * w4.w;
                    }
                }
            }
        }
        #pragma unroll
        for (int j = 0; j < 4; j++) {
            int co = 4 * q + j;
            float g  = bn[co];
            float b  = bn[CO + co];
            float mu = bn[2 * CO + co];
            float vr = bn[3 * CO + co];
            float sc = g * rsqrtf(vr + 1e-3f);
            float sh = b - mu * sc;
            float val = fmaxf(acc[j] * sc + sh, 0.0f);
            out[((co * D + z) * (long)H + y) * W + x] = val;
        }
    }
}

// ---------------- dense tiled conv + BN + ReLU + mask (f32x2 inner loop) ----------------
// Identical launch geometry to R4; ONLY the inner arithmetic changed to FFMA2.
// block = (CO/4, OW/V, YB): thread computes V consecutive-x voxels x 4 channels.
template<int CI, int CO, int V, int YB,
         int KD, int KH, int KW, int SD, int SH, int SW, int PD, int PH, int PW>
__global__ void __launch_bounds__(352, 2)
conv_dense_kernel(const float* __restrict__ in, const float* __restrict__ wr,
                  const float* __restrict__ bn, const float* __restrict__ omask,
                  float* __restrict__ out,
                  int ID, int IH, int IW, int OD, int OH, int OW) {
    constexpr int NSEG = (V - 1) * SW + KW;
    const int q  = threadIdx.x;                    // channel quad
    const int x0 = threadIdx.y * V;
    const int y  = blockIdx.y * YB + threadIdx.z;
    const int z  = blockIdx.z;
    if (y >= OH || x0 >= OW) return;

    float m[V];
    const int obase = (z * OH + y) * OW;
    float msum = 0.0f;
    #pragma unroll
    for (int v = 0; v < V; v++) {
        m[v] = (x0 + v < OW) ? omask[obase + x0 + v] : 0.0f;
        msum += m[v];
    }
    const bool any = msum > 0.0f;

    ull acc[V][2];   // two f32x2 pairs = 4 output channels
    #pragma unroll
    for (int v = 0; v < V; v++) { acc[v][0] = 0ull; acc[v][1] = 0ull; }

    if (any) {
        const int zi0 = z * SD - PD;
        const int yi0 = y * SH - PH;
        const int xi0 = x0 * SW - PW;
        for (int ci = 0; ci < CI; ci++) {
            #pragma unroll
            for (int kz = 0; kz < KD; kz++) {
                int zi = zi0 + kz; if ((unsigned)zi >= (unsigned)ID) continue;
                #pragma unroll
                for (int ky = 0; ky < KH; ky++) {
                    int yi = yi0 + ky; if ((unsigned)yi >= (unsigned)IH) continue;
                    const float* __restrict__ prow = in + ((ci * ID + zi) * (long)IH + yi) * IW;
                    ull iv2[NSEG];
                    #pragma unroll
                    for (int s = 0; s < NSEG; s++) {
                        int xi = xi0 + s;
                        float f = ((unsigned)xi < (unsigned)IW) ? __ldg(prow + xi) : 0.0f;
                        iv2[s] = f2_dup(f);
                    }
                    const float* __restrict__ wrow =
                        wr + ((ci * KD + kz) * KH + ky) * KW * CO + 4 * q;
                    #pragma unroll
                    for (int kx = 0; kx < KW; kx++) {
                        // one 128-bit weight load -> two f32x2 operands
                        union { float4 f; ull u[2]; } wu;
                        wu.f = *reinterpret_cast<const float4*>(wrow + kx * CO);
                        #pragma unroll
                        for (int v = 0; v < V; v++) {
                            ull iv = iv2[v * SW + kx];
                            FMA_F32X2(acc[v][0], iv, wu.u[0], acc[v][0]);
                            FMA_F32X2(acc[v][1], iv, wu.u[1], acc[v][1]);
                        }
                    }
                }
            }
        }
    }

    #pragma unroll
    for (int j = 0; j < 2; j++) {
        int ca = 4 * q + 2 * j, cb = ca + 1;
        float sca = bn[ca] * rsqrtf(bn[3 * CO + ca] + 1e-3f);
        float sha = bn[CO + ca] - bn[2 * CO + ca] * sca;
        float scb = bn[cb] * rsqrtf(bn[3 * CO + cb] + 1e-3f);
        float shb = bn[CO + cb] - bn[2 * CO + cb] * scb;
        #pragma unroll
        for (int v = 0; v < V; v++) {
            int x = x0 + v;
            if (x < OW) {
                float a0, a1; f2_unpack(acc[v][j], a0, a1);
                bool act = m[v] > 0.0f;
                out[((ca * OD + z) * (long)OH + y) * OW + x] =
                    act ? fmaxf(fmaf(a0, sca, sha), 0.0f) : 0.0f;
                out[((cb * OD + z) * (long)OH + y) * OW + x] =
                    act ? fmaxf(fmaf(a1, scb, shb), 0.0f) : 0.0f;
            }
        }
    }
}

// ---------------- launch ----------------
extern "C" void kernel_launch(void* const* d_in, const int* in_sizes, int n_in,
                              void* d_out, int out_size) {
    const float* x    = (const float*)d_in[0];
    const float* mask = (const float*)d_in[1];
    WPtrs wp;
    const float* B_[12];
    for (int i = 0; i < 12; i++) {
        wp.w[i] = (const float*)d_in[2 + 2 * i];
        B_[i]   = (const float*)d_in[3 + 2 * i];
    }
    float* out = (float*)d_out;

    float *bufA, *bufB, *wr, *m2, *m3, *m4, *m5;
    int* cntp;
    cudaGetSymbolAddress((void**)&bufA, g_bufA);
    cudaGetSymbolAddress((void**)&bufB, g_bufB);
    cudaGetSymbolAddress((void**)&wr,   g_wr);
    cudaGetSymbolAddress((void**)&m2,   g_mask2);
    cudaGetSymbolAddress((void**)&m3,   g_mask3);
    cudaGetSymbolAddress((void**)&m4,   g_mask4);
    cudaGetSymbolAddress((void**)&m5,   g_mask5);
    cudaGetSymbolAddress((void**)&cntp, g_cnt);

    static const int off[12] = {0, 1728, 8640, 22464, 50112, 77760, 133056,
                                243648, 354240, 464832, 575424, 686016};

    cudaMemsetAsync(cntp, 0, sizeof(int), 0);
    cudaMemsetAsync(bufA, 0, sizeof(float) * 16 * (size_t)N1, 0);
    cudaMemsetAsync(bufB, 0, sizeof(float) * 16 * (size_t)N1, 0);

    prep_w_all<<<(710592 + 255) / 256, 256>>>(wp, wr);
    compact_kernel<<<(N1 + 255) / 256, 256>>>(mask);

    subm_gather_kernel<4, 16><<<1024, dim3(4, 32)>>>(x, wr + off[0], B_[0], bufA, D1, H1, W1);
    subm_gather_kernel<16, 16><<<1024, dim3(4, 32)>>>(bufA, wr + off[1], B_[1], bufB, D1, H1, W1);

    // launch 4: mask2 ; launch 5: L2 dense conv (ncu -s 5 captures this)
    mask_pool_kernel<<<(N2 + 255) / 256, 256>>>(mask, m2, D1, H1, W1, D2, H2, W2,
                                                3, 3, 3, 2, 2, 2, 1, 1, 1);
    conv_dense_kernel<16, 32, 4, 2, 3, 3, 3, 2, 2, 2, 1, 1, 1>
        <<<dim3(1, (H2 + 1) / 2, D2), dim3(8, 22, 2)>>>(bufB, wr + off[2], B_[2], m2, bufA,
                                                        D1, H1, W1, D2, H2, W2);
    conv_dense_kernel<32, 32, 4, 2, 3, 3, 3, 1, 1, 1, 1, 1, 1>
        <<<dim3(1, (H2 + 1) / 2, D2), dim3(8, 22, 2)>>>(bufA, wr + off[3], B_[3], m2, bufB,
                                                        D2, H2, W2, D2, H2, W2);
    conv_dense_kernel<32, 32, 4, 2, 3, 3, 3, 1, 1, 1, 1, 1, 1>
        <<<dim3(1, (H2 + 1) / 2, D2), dim3(8, 22, 2)>>>(bufB, wr + off[4], B_[4], m2, bufA,
                                                        D2, H2, W2, D2, H2, W2);

    mask_pool_kernel<<<(N3 + 255) / 256, 256>>>(m2, m3, D2, H2, W2, D3, H3, W3,
                                                3, 3, 3, 2, 2, 2, 1, 1, 1);
    conv_dense_kernel<32, 64, 4, 2, 3, 3, 3, 2, 2, 2, 1, 1, 1>
        <<<dim3(1, (H3 + 1) / 2, D3), dim3(16, 11, 2)>>>(bufA, wr + off[5], B_[5], m3, bufB,
                                                         D2, H2, W2, D3, H3, W3);
    conv_dense_kernel<64, 64, 4, 2, 3, 3, 3, 1, 1, 1, 1, 1, 1>
        <<<dim3(1, (H3 + 1) / 2, D3), dim3(16, 11, 2)>>>(bufB, wr + off[6], B_[6], m3, bufA,
                                                         D3, H3, W3, D3, H3, W3);
    conv_dense_kernel<64, 64, 4, 2, 3, 3, 3, 1, 1, 1, 1, 1, 1>
        <<<dim3(1, (H3 + 1) / 2, D3), dim3(16, 11, 2)>>>(bufA, wr + off[7], B_[7], m3, bufB,
                                                         D3, H3, W3, D3, H3, W3);

    mask_pool_kernel<<<(N4 + 255) / 256, 256>>>(m3, m4, D3, H3, W3, D4, H4, W4,
                                                3, 3, 3, 2, 2, 2, 0, 1, 1);
    conv_dense_kernel<64, 64, 2, 2, 3, 3, 3, 2, 2, 2, 0, 1, 1>
        <<<dim3(1, (H4 + 1) / 2, D4), dim3(16, 11, 2)>>>(bufB, wr + off[8], B_[8], m4, bufA,
                                                         D3, H3, W3, D4, H4, W4);
    conv_dense_kernel<64, 64, 2, 2, 3, 3, 3, 1, 1, 1, 1, 1, 1>
        <<<dim3(1, (H4 + 1) / 2, D4), dim3(16, 11, 2)>>>(bufA, wr + off[9], B_[9], m4, bufB,
                                                         D4, H4, W4, D4, H4, W4);
    conv_dense_kernel<64, 64, 2, 2, 3, 3, 3, 1, 1, 1, 1, 1, 1>
        <<<dim3(1, (H4 + 1) / 2, D4), dim3(16, 11, 2)>>>(bufB, wr + off[10], B_[10], m4, bufA,
                                                         D4, H4, W4, D4, H4, W4);

    mask_pool_kernel<<<(N5 + 255) / 256, 256>>>(m4, m5, D4, H4, W4, D5, H5, W5,
                                                3, 1, 1, 2, 1, 1, 0, 0, 0);
    conv_dense_kernel<64, 128, 2, 1, 3, 1, 1, 2, 1, 1, 0, 0, 0>
        <<<dim3(1, H5, D5), dim3(32, 11, 1)>>>(bufA, wr + off[11], B_[11], m5, out,
                                               D4, H4, W4, D5, H5, W5);
}